// round 15
// baseline (speedup 1.0000x reference)
#include <cuda_runtime.h>
#include <cuda_bf16.h>
#include <cstdint>

// Problem dims
#define B_    256
#define T_    100
#define FIN   784
#define FHID  500
#define FOUT  10
#define NTOK  25600   // B_*T_

// Neuron constants
#define EMF  0.7788007830714049f
#define A1F  1.1466802242428472f
#define A2F  -0.2865047968601901f

typedef __nv_bfloat16 bf16;

// ---------------------------------------------------------------------------
// Scratch (device globals; no allocation allowed)
// ---------------------------------------------------------------------------
__device__ float g_ann [NTOK * 1000];   // [n,1000] fp32
__device__ float g_cur2[NTOK * FHID];   // [n,500]
__device__ float g_psp3[NTOK * FHID];   // [n,500]
__device__ float g_cur3[NTOK * FOUT];   // [n,10]
// GEMM1 int8 operands: W1 signed digits (scale 2^25), x unsigned limbs (2^24)
__device__ signed char  g_w1d[3][1024 * 800];   // digit planes, 0 = low
__device__ unsigned char g_xl [3][NTOK * 800];  // limb planes, 0 = low
// GEMM2 bf16x3 split planes (proven R10 path)
__device__ bf16 g_w2p[3][512 * 512];
__device__ bf16 g_p2p[3][NTOK * 512];

// ---------------------------------------------------------------------------
// Helpers
// ---------------------------------------------------------------------------
__device__ __forceinline__ uint32_t smem_u32(const void* p) {
    uint32_t a;
    asm("{ .reg .u64 t; cvta.to.shared.u64 t, %1; cvt.u32.u64 %0, t; }"
        : "=r"(a) : "l"(p));
    return a;
}
__device__ __forceinline__ void ldsm4(uint32_t* r, uint32_t addr) {
    asm volatile("ldmatrix.sync.aligned.m8n8.x4.shared.b16 {%0,%1,%2,%3}, [%4];"
        : "=r"(r[0]), "=r"(r[1]), "=r"(r[2]), "=r"(r[3]) : "r"(addr));
}
__device__ __forceinline__ void mma_bf16(float* d, const uint32_t* a, const uint32_t* b) {
    asm volatile("mma.sync.aligned.m16n8k16.row.col.f32.bf16.bf16.f32 "
        "{%0,%1,%2,%3}, {%4,%5,%6,%7}, {%8,%9}, {%0,%1,%2,%3};"
        : "+f"(d[0]), "+f"(d[1]), "+f"(d[2]), "+f"(d[3])
        : "r"(a[0]), "r"(a[1]), "r"(a[2]), "r"(a[3]), "r"(b[0]), "r"(b[1]));
}
__device__ __forceinline__ void mma_s8u8(int* d, const uint32_t* a, const uint32_t* b) {
    asm volatile("mma.sync.aligned.m16n8k32.row.col.s32.s8.u8.s32 "
        "{%0,%1,%2,%3}, {%4,%5,%6,%7}, {%8,%9}, {%0,%1,%2,%3};"
        : "+r"(d[0]), "+r"(d[1]), "+r"(d[2]), "+r"(d[3])
        : "r"(a[0]), "r"(a[1]), "r"(a[2]), "r"(a[3]), "r"(b[0]), "r"(b[1]));
}
#define CP16(dst, src) \
    asm volatile("cp.async.cg.shared.global [%0], [%1], 16;" :: "r"(dst), "l"(src))
#define CP_COMMIT() asm volatile("cp.async.commit_group;" ::: "memory")
#define CP_WAIT0()  asm volatile("cp.async.wait_group 0;" ::: "memory")

__device__ __forceinline__ void split3(float x, bf16& b0, bf16& b1, bf16& b2) {
    b0 = __float2bfloat16_rn(x);
    float r1 = __fsub_rn(x, __bfloat162float(b0));
    b1 = __float2bfloat16_rn(r1);
    b2 = __float2bfloat16_rn(__fsub_rn(r1, __bfloat162float(b1)));
}

// ---------------------------------------------------------------------------
// W1 -> signed base-256 digits, scale 2^25 (|w| <= 0.18 -> |v| < 2^23)
// ---------------------------------------------------------------------------
__global__ __launch_bounds__(256)
void split_w1_i8(const float* __restrict__ W) {
    int i = blockIdx.x * 256 + threadIdx.x;
    if (i >= 1024 * 800) return;
    int o = i / 800, k = i - o * 800;
    float w = (o < 1000 && k < FIN) ? W[o * FIN + k] : 0.f;
    int v = __float2int_rn(__fmul_rn(w, 33554432.0f));   // 2^25
    int d0 = ((v + 128) & 255) - 128;  int v1 = (v - d0) >> 8;
    int d1 = ((v1 + 128) & 255) - 128; int d2 = (v1 - d1) >> 8;
    g_w1d[0][i] = (signed char)d0;
    g_w1d[1][i] = (signed char)d1;
    g_w1d[2][i] = (signed char)d2;
}

// ---------------------------------------------------------------------------
// W2 -> bf16x3 (proven path)
// ---------------------------------------------------------------------------
__global__ __launch_bounds__(256)
void split_w2_kernel(const float* __restrict__ W) {
    int i = blockIdx.x * 256 + threadIdx.x;
    if (i >= 512 * 512) return;
    int o = i / 512, k = i - o * 512;
    float v = (o < FHID && k < FHID) ? W[o * FHID + k] : 0.f;
    bf16 b0, b1, b2;
    split3(v, b0, b1, b2);
    g_w2p[0][i] = b0; g_w2p[1][i] = b1; g_w2p[2][i] = b2;
}

// ---------------------------------------------------------------------------
// Inputs [b,784,t] -> transpose + 24-bit u8 limbs -> g_xl [n, 800]
// ---------------------------------------------------------------------------
__global__ __launch_bounds__(256)
void transpose_inputs_i8(const float* __restrict__ inp) {
    __shared__ float s[32][105];
    const int b  = blockIdx.y;
    const int k0 = blockIdx.x * 32;
    for (int i = threadIdx.x; i < 3200; i += 256) {
        int kk = i / 100, t = i - kk * 100;
        int k = k0 + kk;
        s[kk][t] = (k < FIN) ? inp[b * (FIN * T_) + k * T_ + t] : 0.f;
    }
    __syncthreads();
    for (int i = threadIdx.x; i < 3200; i += 256) {
        int t = i >> 5, kk = i & 31;
        unsigned u = __float2uint_rn(__fmul_rn(s[kk][t], 16777216.0f));  // 2^24
        if (u > 16777215u) u = 16777215u;
        int idx = (b * T_ + t) * 800 + k0 + kk;
        g_xl[0][idx] = (unsigned char)(u & 255u);
        g_xl[1][idx] = (unsigned char)((u >> 8) & 255u);
        g_xl[2][idx] = (unsigned char)(u >> 16);
    }
}

// ---------------------------------------------------------------------------
// GEMM1 on IMMA s8/u8, exact s32 accumulation, 8 limb products, 4 weight sets.
// CTA 128(o) x 64(n), BK=32, 8 warps, warp tile 64x16, 1 CTA/SM.
// smem: A 2buf x 3pl x 128 x 48B = 36864; B 2 x 3 x 64 x 48 = 18432; tot 55296.
// ---------------------------------------------------------------------------
__global__ __launch_bounds__(256, 1)
void gemm1_i8(const float* __restrict__ bias) {
    constexpr int KP = 800, NCH = 25;

    extern __shared__ __align__(16) char smem[];
    const uint32_t sbase = smem_u32(smem);
    const uint32_t sbB   = sbase + 36864;

    const int tid  = threadIdx.x;
    const int lane = tid & 31;
    const int wid  = tid >> 5;
    const int warp_o = wid >> 2;   // 0..1
    const int warp_n = wid & 3;    // 0..3
    const int o0 = blockIdx.x * 128;
    const int n0 = blockIdx.y * 64;

    // A loader: row = tid>>1 (0..127), half = tid&1
    const int ra = tid >> 1, ha = tid & 1;
    const uint32_t sts_a = sbase + ra * 48 + ha * 16;   // + buf*18432 + pl*6144
    const signed char* gaW[3] = {
        g_w1d[0] + (o0 + ra) * KP + ha * 16,
        g_w1d[1] + (o0 + ra) * KP + ha * 16,
        g_w1d[2] + (o0 + ra) * KP + ha * 16 };
    // B loader: threads 0-127: row = tid>>1 (0..63), half
    const int rb = (tid & 127) >> 1, hb = tid & 1;
    const uint32_t sts_b = sbB + rb * 48 + hb * 16;     // + buf*9216 + pl*3072
    const unsigned char* gbX[3] = {
        g_xl[0] + (n0 + rb) * KP + hb * 16,
        g_xl[1] + (n0 + rb) * KP + hb * 16,
        g_xl[2] + (n0 + rb) * KP + hb * 16 };
    const bool do_b = (tid < 128);

    // 4 s32 accumulator sets by weight s=1..4 (lo*lo dropped)
    int acc1[4][2][4], acc2[4][2][4], acc3[4][2][4], acc4[4][2][4];
    #pragma unroll
    for (int mt = 0; mt < 4; mt++)
        #pragma unroll
        for (int nt = 0; nt < 2; nt++)
            #pragma unroll
            for (int i = 0; i < 4; i++) {
                acc1[mt][nt][i] = 0; acc2[mt][nt][i] = 0;
                acc3[mt][nt][i] = 0; acc4[mt][nt][i] = 0;
            }

    auto load_chunk = [&](int c, int buf) {
        const int ko = c * 32;
        #pragma unroll
        for (int pl = 0; pl < 3; pl++) {
            CP16(sts_a + buf * 18432 + pl * 6144, gaW[pl] + ko);
            if (do_b) CP16(sts_b + buf * 9216 + pl * 3072, gbX[pl] + ko);
        }
    };

    // ldmatrix addressing (48B pitch, conflict-free)
    const uint32_t a_lane = (uint32_t)((lane & 15) * 48 + (lane >> 4) * 16);
    const uint32_t b_lane = (uint32_t)((lane & 7) * 48 + ((lane >> 3) & 1) * 16 + (lane >> 4) * 384);
    const uint32_t abase0 = sbase + warp_o * 3072 + a_lane;   // 64 rows * 48
    const uint32_t bbase0 = sbB + warp_n * 768 + b_lane;      // 16 rows * 48

    load_chunk(0, 0);
    CP_COMMIT();
    CP_WAIT0();
    __syncthreads();

    for (int c = 0; c < NCH; c++) {
        const int buf = c & 1;
        if (c + 1 < NCH) { load_chunk(c + 1, buf ^ 1); CP_COMMIT(); }

        uint32_t af[3][4][4];   // [w digit][mt][4]
        #pragma unroll
        for (int pl = 0; pl < 3; pl++)
            #pragma unroll
            for (int mt = 0; mt < 4; mt++)
                ldsm4(af[pl][mt], abase0 + buf * 18432 + pl * 6144 + mt * 768);
        uint32_t bfr[3][4];     // [x limb][4]  (nt0 = regs 0,1; nt1 = regs 2,3)
        #pragma unroll
        for (int pl = 0; pl < 3; pl++)
            ldsm4(bfr[pl], bbase0 + buf * 9216 + pl * 3072);

        #define PROD(ai, bj, ACC) { \
            _Pragma("unroll") \
            for (int mt = 0; mt < 4; mt++) \
                _Pragma("unroll") \
                for (int nt = 0; nt < 2; nt++) \
                    mma_s8u8(ACC[mt][nt], af[ai][mt], &bfr[bj][nt * 2]); }

        PROD(0, 1, acc1)  PROD(1, 0, acc1)
        PROD(0, 2, acc2)  PROD(1, 1, acc2)  PROD(2, 0, acc2)
        PROD(1, 2, acc3)  PROD(2, 1, acc3)
        PROD(2, 2, acc4)
        #undef PROD

        if (c + 1 < NCH) CP_WAIT0();
        __syncthreads();
    }

    // ---- epilogue: exact int64 combine -> fp32, bias, relu; smem transpose ----
    float* es = reinterpret_cast<float*>(smem);   // [64][132] = 33792 B
    #pragma unroll
    for (int mt = 0; mt < 4; mt++)
        #pragma unroll
        for (int nt = 0; nt < 2; nt++)
            #pragma unroll
            for (int i = 0; i < 4; i++) {
                long long S = ((long long)acc4[mt][nt][i] << 24)
                            + ((long long)acc3[mt][nt][i] << 16)
                            + ((long long)acc2[mt][nt][i] << 8)
                            +  (long long)acc1[mt][nt][i];
                float v = __fmul_rn((float)S, 4.5474735088646412e-13f);  // 2^-41
                int ol = warp_o * 64 + mt * 16 + (lane >> 2) + 8 * (i >> 1);
                int nl = warp_n * 16 + nt * 8 + 2 * (lane & 3) + (i & 1);
                es[nl * 132 + ol] = v;
            }
    __syncthreads();
    for (int it = tid; it < 64 * 32; it += 256) {
        int nl = it >> 5;
        int c4 = (it & 31) * 4;
        int o  = o0 + c4;
        if (o < 1000) {
            float4 v  = *reinterpret_cast<const float4*>(&es[nl * 132 + c4]);
            float4 bv = *reinterpret_cast<const float4*>(&bias[o]);
            v.x = fmaxf(__fadd_rn(v.x, bv.x), 0.f);
            v.y = fmaxf(__fadd_rn(v.y, bv.y), 0.f);
            v.z = fmaxf(__fadd_rn(v.z, bv.z), 0.f);
            v.w = fmaxf(__fadd_rn(v.w, bv.w), 0.f);
            *reinterpret_cast<float4*>(&g_ann[(n0 + nl) * 1000 + o]) = v;
        }
    }
}

// ---------------------------------------------------------------------------
// GEMM2 on HMMA bf16x3, 6 products, chunked RN accumulation (R10, passing).
// CTA 128(o) x 64(n), 8 warps, warp tile 64x16, 2 CTAs/SM.
// ---------------------------------------------------------------------------
__global__ __launch_bounds__(256, 2)
void gemm2_b3(const float* __restrict__ bias) {
    constexpr int O = FHID, KP = 512, NCH = 16;
    extern __shared__ __align__(16) char smem[];
    const uint32_t sbase = smem_u32(smem);
    const uint32_t sbB   = sbase + 61440;

    const int tid  = threadIdx.x;
    const int lane = tid & 31;
    const int wid  = tid >> 5;
    const int warp_o = wid >> 2;
    const int warp_n = wid & 3;
    const int o0 = blockIdx.x * 128;
    const int n0 = blockIdx.y * 64;

    const int ra  = tid >> 1;
    const int kh  = (tid & 1) * 16;
    const uint32_t sts_a = sbase + ra * 80 + kh * 2;
    const bf16* ga[3] = { g_w2p[0] + (o0 + ra) * KP + kh, g_w2p[1] + (o0 + ra) * KP + kh,
                          g_w2p[2] + (o0 + ra) * KP + kh };
    const int rb = tid >> 2;
    const int kq = (tid & 3) * 8;
    const uint32_t sts_b = sbB + rb * 80 + kq * 2;
    const bf16* gb[3] = { g_p2p[0] + (n0 + rb) * KP + kq, g_p2p[1] + (n0 + rb) * KP + kq,
                          g_p2p[2] + (n0 + rb) * KP + kq };

    float accT[4][2][4];
    #pragma unroll
    for (int mt = 0; mt < 4; mt++)
        #pragma unroll
        for (int nt = 0; nt < 2; nt++)
            #pragma unroll
            for (int i = 0; i < 4; i++) accT[mt][nt][i] = 0.f;

    auto load_chunk = [&](int c, int buf) {
        const int ko = c * 32;
        #pragma unroll
        for (int pl = 0; pl < 3; pl++) {
            const uint32_t da = sts_a + buf * 30720 + pl * 10240;
            CP16(da,      ga[pl] + ko);
            CP16(da + 16, ga[pl] + ko + 8);
            const uint32_t db = sts_b + buf * 15360 + pl * 5120;
            CP16(db, gb[pl] + ko);
        }
    };

    const uint32_t a_lane = (uint32_t)((lane & 15) * 80 + (lane >> 4) * 16);
    const uint32_t b_lane = (uint32_t)((lane & 7) * 80 + ((lane >> 3) & 1) * 16 + (lane >> 4) * 640);
    const uint32_t abase0 = sbase + warp_o * 5120 + a_lane;
    const uint32_t bbase0 = sbB + warp_n * 1280 + b_lane;

    load_chunk(0, 0);
    CP_COMMIT();
    CP_WAIT0();
    __syncthreads();

    for (int c = 0; c < NCH; c++) {
        const int buf = c & 1;
        if (c + 1 < NCH) { load_chunk(c + 1, buf ^ 1); CP_COMMIT(); }

        float accC[4][2][4];
        #pragma unroll
        for (int mt = 0; mt < 4; mt++)
            #pragma unroll
            for (int nt = 0; nt < 2; nt++)
                #pragma unroll
                for (int i = 0; i < 4; i++) accC[mt][nt][i] = 0.f;

        #pragma unroll
        for (int ks = 0; ks < 2; ks++) {
            uint32_t bfr[3][4];
            const uint32_t bb = bbase0 + buf * 15360 + ks * 32;
            #pragma unroll
            for (int p = 0; p < 3; p++)
                ldsm4(bfr[p], bb + p * 5120);

            const uint32_t ab = abase0 + buf * 30720 + ks * 32;
            uint32_t af[4][4];
            #pragma unroll
            for (int mt = 0; mt < 4; mt++) ldsm4(af[mt], ab + mt * 1280);
            #pragma unroll
            for (int pb = 0; pb < 3; pb++)
                #pragma unroll
                for (int mt = 0; mt < 4; mt++)
                    #pragma unroll
                    for (int nt = 0; nt < 2; nt++)
                        mma_bf16(accC[mt][nt], af[mt], &bfr[pb][nt * 2]);
            #pragma unroll
            for (int mt = 0; mt < 4; mt++) ldsm4(af[mt], ab + 10240 + mt * 1280);
            #pragma unroll
            for (int pb = 0; pb < 2; pb++)
                #pragma unroll
                for (int mt = 0; mt < 4; mt++)
                    #pragma unroll
                    for (int nt = 0; nt < 2; nt++)
                        mma_bf16(accC[mt][nt], af[mt], &bfr[pb][nt * 2]);
            #pragma unroll
            for (int mt = 0; mt < 4; mt++) ldsm4(af[mt], ab + 20480 + mt * 1280);
            #pragma unroll
            for (int mt = 0; mt < 4; mt++)
                #pragma unroll
                for (int nt = 0; nt < 2; nt++)
                    mma_bf16(accC[mt][nt], af[mt], &bfr[0][nt * 2]);
        }

        #pragma unroll
        for (int mt = 0; mt < 4; mt++)
            #pragma unroll
            for (int nt = 0; nt < 2; nt++)
                #pragma unroll
                for (int i = 0; i < 4; i++)
                    accT[mt][nt][i] = __fadd_rn(accT[mt][nt][i], accC[mt][nt][i]);

        if (c + 1 < NCH) CP_WAIT0();
        __syncthreads();
    }

    float* es = reinterpret_cast<float*>(smem);   // [64][132]
    #pragma unroll
    for (int mt = 0; mt < 4; mt++)
        #pragma unroll
        for (int nt = 0; nt < 2; nt++)
            #pragma unroll
            for (int i = 0; i < 4; i++) {
                int ol = warp_o * 64 + mt * 16 + (lane >> 2) + 8 * (i >> 1);
                int nl = warp_n * 16 + nt * 8 + 2 * (lane & 3) + (i & 1);
                es[nl * 132 + ol] = accT[mt][nt][i];
            }
    __syncthreads();
    for (int it = tid; it < 64 * 32; it += 256) {
        int nl = it >> 5;
        int c4 = (it & 31) * 4;
        int o  = o0 + c4;
        if (o < O) {
            float4 v  = *reinterpret_cast<const float4*>(&es[nl * 132 + c4]);
            float4 bv = *reinterpret_cast<const float4*>(&bias[o]);
            v.x = __fadd_rn(v.x, bv.x);
            v.y = __fadd_rn(v.y, bv.y);
            v.z = __fadd_rn(v.z, bv.z);
            v.w = __fadd_rn(v.w, bv.w);
            *reinterpret_cast<float4*>(&g_cur2[(n0 + nl) * O + o]) = v;
        }
    }
}

// ---------------------------------------------------------------------------
// Threefry2x32-20, key=(0,42); partitionable path (verified bit-exact)
// ---------------------------------------------------------------------------
__device__ __forceinline__ unsigned rotl32(unsigned x, int r) {
    return (x << r) | (x >> (32 - r));
}
__device__ __forceinline__ void threefry2x32_k42(unsigned c0, unsigned c1,
                                                 unsigned& o0, unsigned& o1) {
    const unsigned k0 = 0u, k1 = 42u;
    const unsigned k2 = 0x1BD11BDAu ^ k0 ^ k1;
    unsigned x0 = c0 + k0;
    unsigned x1 = c1 + k1;
#define TFR(r) { x0 += x1; x1 = rotl32(x1, (r)); x1 ^= x0; }
    TFR(13) TFR(15) TFR(26) TFR(6)
    x0 += k1; x1 += k2 + 1u;
    TFR(17) TFR(29) TFR(16) TFR(24)
    x0 += k2; x1 += k0 + 2u;
    TFR(13) TFR(15) TFR(26) TFR(6)
    x0 += k0; x1 += k1 + 3u;
    TFR(17) TFR(29) TFR(16) TFR(24)
    x0 += k1; x1 += k2 + 4u;
    TFR(13) TFR(15) TFR(26) TFR(6)
    x0 += k2; x1 += k0 + 5u;
#undef TFR
    o0 = x0; o1 = x1;
}
__device__ __forceinline__ float xla_erfinv32(float x) {
    float w = -log1pf(__fmul_rn(-x, x));
    float p;
    if (w < 5.0f) {
        w = __fadd_rn(w, -2.5f);
        p = 2.81022636e-08f;
        p = __fadd_rn(__fmul_rn(p, w),  3.43273939e-07f);
        p = __fadd_rn(__fmul_rn(p, w), -3.5233877e-06f);
        p = __fadd_rn(__fmul_rn(p, w), -4.39150654e-06f);
        p = __fadd_rn(__fmul_rn(p, w),  0.00021858087f);
        p = __fadd_rn(__fmul_rn(p, w), -0.00125372503f);
        p = __fadd_rn(__fmul_rn(p, w), -0.00417768164f);
        p = __fadd_rn(__fmul_rn(p, w),  0.246640727f);
        p = __fadd_rn(__fmul_rn(p, w),  1.50140941f);
    } else {
        w = __fadd_rn(sqrtf(w), -3.0f);
        p = -0.000200214257f;
        p = __fadd_rn(__fmul_rn(p, w),  0.000100950558f);
        p = __fadd_rn(__fmul_rn(p, w),  0.00134934322f);
        p = __fadd_rn(__fmul_rn(p, w), -0.00367342844f);
        p = __fadd_rn(__fmul_rn(p, w),  0.00573950773f);
        p = __fadd_rn(__fmul_rn(p, w), -0.0076224613f);
        p = __fadd_rn(__fmul_rn(p, w),  0.00943887047f);
        p = __fadd_rn(__fmul_rn(p, w),  1.00167406f);
        p = __fadd_rn(__fmul_rn(p, w),  2.83297682f);
    }
    return __fmul_rn(p, x);
}
__device__ __forceinline__ float jax_normal_eps(unsigned i) {
    unsigned r0, r1;
    threefry2x32_k42(0u, i, r0, r1);
    unsigned bits = r0 ^ r1;
    float f = __fadd_rn(__uint_as_float((bits >> 9) | 0x3f800000u), -1.0f);
    float u = fmaxf(-0.99999994f, __fadd_rn(__fmul_rn(f, 2.0f), -0.99999994f));
    return __fmul_rn(1.41421356237309515f, xla_erfinv32(u));
}

// ---------------------------------------------------------------------------
// coding = mu + eps * exp(0.5*ln_var); psp2 = dual-exp IIR; emit bf16x3 planes
// ---------------------------------------------------------------------------
__global__ __launch_bounds__(256)
void coding_psp2_kernel() {
    int idx = blockIdx.x * blockDim.x + threadIdx.x;
    if (idx >= B_ * FHID) return;
    int b = idx / FHID;
    int f = idx - b * FHID;
    const float* mu = g_ann + b * (T_ * 1000) + f;
    const float* lv = mu + FHID;
    if (f < 12) {
        bf16 z = __float2bfloat16(0.f);
        for (int t = 0; t < T_; t++) {
            int zi = (b * T_ + t) * 512 + FHID + f;
            g_p2p[0][zi] = z; g_p2p[1][zi] = z; g_p2p[2][zi] = z;
        }
    }
    unsigned base = (unsigned)idx * 100u;
    float y1 = 0.f, y2 = 0.f;
    #pragma unroll 4
    for (int t = 0; t < T_; t++) {
        float eps = jax_normal_eps(base + (unsigned)t);
        float sc  = expf(__fmul_rn(0.5f, lv[t * 1000]));
        float cod = __fadd_rn(mu[t * 1000], __fmul_rn(eps, sc));
        float y   = __fadd_rn(__fadd_rn(__fmul_rn(A1F, y1), __fmul_rn(A2F, y2)), cod);
        bf16 b0, b1, b2;
        split3(y, b0, b1, b2);
        int oi = (b * T_ + t) * 512 + f;
        g_p2p[0][oi] = b0;
        g_p2p[1][oi] = b1;
        g_p2p[2][oi] = b2;
        y2 = y1; y1 = y;
    }
}

// ---------------------------------------------------------------------------
// LIF2 + IIR -> g_psp3 [n,500]
// ---------------------------------------------------------------------------
__global__ __launch_bounds__(256)
void lif2_psp3_kernel() {
    int idx = blockIdx.x * blockDim.x + threadIdx.x;
    if (idx >= B_ * FHID) return;
    int b = idx / FHID;
    int f = idx - b * FHID;
    const float* c = g_cur2 + b * (T_ * FHID) + f;
    float* out     = g_psp3 + b * (T_ * FHID) + f;
    float v = 0.f, s = 0.f, y1 = 0.f, y2 = 0.f;
    #pragma unroll 4
    for (int t = 0; t < T_; t++) {
        float vn = __fadd_rn(__fmul_rn(__fmul_rn(v, EMF), __fsub_rn(1.0f, s)), c[t * FHID]);
        float spk = (vn > 1.0f) ? 1.0f : 0.0f;
        v = vn; s = spk;
        float y = __fadd_rn(__fadd_rn(__fmul_rn(A1F, y1), __fmul_rn(A2F, y2)), spk);
        out[t * FHID] = y;
        y2 = y1; y1 = y;
    }
}

// ---------------------------------------------------------------------------
// GEMM3 (fp32, tiny)
// ---------------------------------------------------------------------------
__global__ __launch_bounds__(256)
void gemm3_kernel(const float* __restrict__ W3, const float* __restrict__ b3) {
    __shared__ __align__(16) float Ws[FOUT * FHID];
    for (int i = threadIdx.x; i < FOUT * FHID; i += 256) Ws[i] = W3[i];
    __syncthreads();
    int n = blockIdx.x * 256 + threadIdx.x;
    float acc[FOUT];
    #pragma unroll
    for (int o = 0; o < FOUT; o++) acc[o] = 0.f;
    const float4* xp = reinterpret_cast<const float4*>(g_psp3 + n * FHID);
    #pragma unroll 5
    for (int k4 = 0; k4 < FHID / 4; k4++) {
        float4 x = xp[k4];
        #pragma unroll
        for (int o = 0; o < FOUT; o++) {
            float4 w = *reinterpret_cast<const float4*>(&Ws[o * FHID + k4 * 4]);
            acc[o] += w.x * x.x;
            acc[o] += w.y * x.y;
            acc[o] += w.z * x.z;
            acc[o] += w.w * x.w;
        }
    }
    #pragma unroll
    for (int o = 0; o < FOUT; o++)
        g_cur3[n * FOUT + o] = __fadd_rn(acc[o], b3[o]);
}

// ---------------------------------------------------------------------------
// LIF3 -> output spikes [b,o,t]
// ---------------------------------------------------------------------------
__global__ __launch_bounds__(256)
void lif3_kernel(float* __restrict__ out) {
    int idx = blockIdx.x * blockDim.x + threadIdx.x;
    if (idx >= B_ * FOUT) return;
    int b = idx / FOUT;
    int o = idx - b * FOUT;
    const float* c = g_cur3 + b * (T_ * FOUT) + o;
    float* op = out + idx * T_;
    float v = 0.f, s = 0.f;
    #pragma unroll 4
    for (int t = 0; t < T_; t++) {
        float vn = __fadd_rn(__fmul_rn(__fmul_rn(v, EMF), __fsub_rn(1.0f, s)), c[t * FOUT]);
        float spk = (vn > 1.0f) ? 1.0f : 0.0f;
        v = vn; s = spk;
        op[t] = spk;
    }
}

// ---------------------------------------------------------------------------
extern "C" void kernel_launch(void* const* d_in, const int* in_sizes, int n_in,
                              void* d_out, int out_size) {
    const float* inputs = (const float*)d_in[0];
    const float* W1     = (const float*)d_in[1];
    const float* b1     = (const float*)d_in[2];
    const float* W2     = (const float*)d_in[3];
    const float* b2     = (const float*)d_in[4];
    const float* W3     = (const float*)d_in[5];
    const float* b3     = (const float*)d_in[6];
    float* out          = (float*)d_out;

    constexpr int G1_SMEM = 55296;
    constexpr int G2_SMEM = 92160;
    cudaFuncSetAttribute(gemm1_i8, cudaFuncAttributeMaxDynamicSharedMemorySize, G1_SMEM);
    cudaFuncSetAttribute(gemm2_b3, cudaFuncAttributeMaxDynamicSharedMemorySize, G2_SMEM);

    // Prep
    split_w1_i8<<<(1024 * 800 + 255) / 256, 256>>>(W1);
    split_w2_kernel<<<(512 * 512 + 255) / 256, 256>>>(W2);
    transpose_inputs_i8<<<dim3(25, 256), 256>>>(inputs);

    // Layer 1 (IMMA exact fixed point)
    gemm1_i8<<<dim3(8, 400), 256, G1_SMEM>>>(b1);
    // coding + IIR -> bf16x3 planes
    coding_psp2_kernel<<<(B_ * FHID + 255) / 256, 256>>>();
    // Layer 2 (bf16x3 HMMA, chunked RN)
    gemm2_b3<<<dim3(4, 400), 256, G2_SMEM>>>(b2);
    // LIF2 + IIR
    lif2_psp3_kernel<<<(B_ * FHID + 255) / 256, 256>>>();
    // Layer 3 + LIF
    gemm3_kernel<<<NTOK / 256, 256>>>(W3, b3);
    lif3_kernel<<<(B_ * FOUT + 255) / 256, 256>>>(out);
}

// round 16
// speedup vs baseline: 2.3009x; 2.3009x over previous
#include <cuda_runtime.h>
#include <cuda_bf16.h>
#include <cstdint>

// Problem dims
#define B_    256
#define T_    100
#define FIN   784
#define FHID  500
#define FOUT  10
#define NTOK  25600   // B_*T_

// Neuron constants
#define EMF  0.7788007830714049f
#define A1F  1.1466802242428472f
#define A2F  -0.2865047968601901f

typedef __nv_bfloat16 bf16;

// ---------------------------------------------------------------------------
// Scratch (device globals; no allocation allowed)
// ---------------------------------------------------------------------------
__device__ float g_ann [NTOK * 1000];   // [n,1000] fp32
__device__ float g_cur2[NTOK * FHID];   // [n,500]
__device__ float g_psp3[NTOK * FHID];   // [n,500]
__device__ float g_cur3[NTOK * FOUT];   // [n,10]
__device__ float g_eps [B_ * FHID * T_]; // precomputed normal eps (12.8M)
// bf16x3 split operand planes (zero-padded to tile multiples)
__device__ bf16 g_w1p[3][1024 * 800];
__device__ bf16 g_w2p[3][512 * 512];
__device__ bf16 g_xp [3][NTOK * 800];
__device__ bf16 g_p2p[3][NTOK * 512];

// ---------------------------------------------------------------------------
// MMA helpers (baseline PTX, valid on plain sm_103 target)
// ---------------------------------------------------------------------------
__device__ __forceinline__ uint32_t smem_u32(const void* p) {
    uint32_t a;
    asm("{ .reg .u64 t; cvta.to.shared.u64 t, %1; cvt.u32.u64 %0, t; }"
        : "=r"(a) : "l"(p));
    return a;
}
__device__ __forceinline__ void ldsm4(uint32_t* r, uint32_t addr) {
    asm volatile("ldmatrix.sync.aligned.m8n8.x4.shared.b16 {%0,%1,%2,%3}, [%4];"
        : "=r"(r[0]), "=r"(r[1]), "=r"(r[2]), "=r"(r[3]) : "r"(addr));
}
__device__ __forceinline__ void mma_bf16(float* d, const uint32_t* a, const uint32_t* b) {
    asm volatile("mma.sync.aligned.m16n8k16.row.col.f32.bf16.bf16.f32 "
        "{%0,%1,%2,%3}, {%4,%5,%6,%7}, {%8,%9}, {%0,%1,%2,%3};"
        : "+f"(d[0]), "+f"(d[1]), "+f"(d[2]), "+f"(d[3])
        : "r"(a[0]), "r"(a[1]), "r"(a[2]), "r"(a[3]), "r"(b[0]), "r"(b[1]));
}
#define CP16(dst, src) \
    asm volatile("cp.async.cg.shared.global [%0], [%1], 16;" :: "r"(dst), "l"(src))
#define CP_COMMIT() asm volatile("cp.async.commit_group;" ::: "memory")
#define CP_WAIT0()  asm volatile("cp.async.wait_group 0;" ::: "memory")

// ---------------------------------------------------------------------------
// bf16x3 split: residual <= ~2^-25 |x|, full fp32 exponent range
// ---------------------------------------------------------------------------
__device__ __forceinline__ void split3(float x, bf16& b0, bf16& b1, bf16& b2) {
    b0 = __float2bfloat16_rn(x);
    float r1 = __fsub_rn(x, __bfloat162float(b0));
    b1 = __float2bfloat16_rn(r1);
    b2 = __float2bfloat16_rn(__fsub_rn(r1, __bfloat162float(b1)));
}

// ---------------------------------------------------------------------------
// Weight pre-split (+ zero padding)
// ---------------------------------------------------------------------------
template<int SEL>
__global__ __launch_bounds__(256)
void split_w_kernel(const float* __restrict__ W) {
    constexpr int O  = SEL ? FHID : 1000;
    constexpr int K  = SEL ? FHID : FIN;
    constexpr int OP = SEL ? 512  : 1024;
    constexpr int KP = SEL ? 512  : 800;
    int i = blockIdx.x * 256 + threadIdx.x;
    if (i >= OP * KP) return;
    int o = i / KP, k = i - o * KP;
    float v = (o < O && k < K) ? W[o * K + k] : 0.f;
    bf16 b0, b1, b2;
    split3(v, b0, b1, b2);
    if (SEL) { g_w2p[0][i] = b0; g_w2p[1][i] = b1; g_w2p[2][i] = b2; }
    else     { g_w1p[0][i] = b0; g_w1p[1][i] = b1; g_w1p[2][i] = b2; }
}

// ---------------------------------------------------------------------------
// Inputs [b,784,t] -> transpose + split3 -> g_xp planes [n, 800]
// ---------------------------------------------------------------------------
__global__ __launch_bounds__(256)
void transpose_split_inputs(const float* __restrict__ inp) {
    __shared__ float s[32][105];
    const int b  = blockIdx.y;
    const int k0 = blockIdx.x * 32;
    for (int i = threadIdx.x; i < 3200; i += 256) {
        int kk = i / 100, t = i - kk * 100;
        int k = k0 + kk;
        s[kk][t] = (k < FIN) ? inp[b * (FIN * T_) + k * T_ + t] : 0.f;
    }
    __syncthreads();
    for (int i = threadIdx.x; i < 3200; i += 256) {
        int t = i >> 5, kk = i & 31;
        bf16 b0, b1, b2;
        split3(s[kk][t], b0, b1, b2);
        int idx = (b * T_ + t) * 800 + k0 + kk;
        g_xp[0][idx] = b0;
        g_xp[1][idx] = b1;
        g_xp[2][idx] = b2;
    }
}

// ---------------------------------------------------------------------------
// GEMM on HMMA, bf16x3 split, chunked RN accumulation (R10, proven 0.0).
// CTA 128(o) x 64(n), BK=32, 8 warps (warp tile 64x16), 2 CTAs/SM.
// ---------------------------------------------------------------------------
template<int SEL>  // 0: O=1000,KP=800, RELU, Y=g_ann; 1: O=500,KP=512, Y=g_cur2
__global__ __launch_bounds__(256, 2)
void gemm_b3(const float* __restrict__ bias) {
    constexpr int O   = SEL ? FHID : 1000;
    constexpr int KP  = SEL ? 512  : 800;
    constexpr int NCH = KP / 32;
    const bf16* __restrict__ A0 = SEL ? g_w2p[0] : g_w1p[0];
    const bf16* __restrict__ A1 = SEL ? g_w2p[1] : g_w1p[1];
    const bf16* __restrict__ A2 = SEL ? g_w2p[2] : g_w1p[2];
    const bf16* __restrict__ B0 = SEL ? g_p2p[0] : g_xp[0];
    const bf16* __restrict__ B1 = SEL ? g_p2p[1] : g_xp[1];
    const bf16* __restrict__ B2 = SEL ? g_p2p[2] : g_xp[2];
    float* __restrict__ Y = SEL ? g_cur2 : g_ann;

    extern __shared__ __align__(16) char smem[];
    const uint32_t sbase = smem_u32(smem);
    const uint32_t sbB   = sbase + 61440;

    const int tid  = threadIdx.x;
    const int lane = tid & 31;
    const int wid  = tid >> 5;
    const int warp_o = wid >> 2;   // 0..1 (64 rows)
    const int warp_n = wid & 3;    // 0..3 (16 cols)
    const int o0 = blockIdx.x * 128;
    const int n0 = blockIdx.y * 64;

    const int ra  = tid >> 1;
    const int kh  = (tid & 1) * 16;
    const uint32_t sts_a = sbase + ra * 80 + kh * 2;
    const bf16* ga[3] = { A0 + (o0 + ra) * KP + kh, A1 + (o0 + ra) * KP + kh,
                          A2 + (o0 + ra) * KP + kh };
    const int rb = tid >> 2;
    const int kq = (tid & 3) * 8;
    const uint32_t sts_b = sbB + rb * 80 + kq * 2;
    const bf16* gb[3] = { B0 + (n0 + rb) * KP + kq, B1 + (n0 + rb) * KP + kq,
                          B2 + (n0 + rb) * KP + kq };

    float accT[4][2][4];
    #pragma unroll
    for (int mt = 0; mt < 4; mt++)
        #pragma unroll
        for (int nt = 0; nt < 2; nt++)
            #pragma unroll
            for (int i = 0; i < 4; i++) accT[mt][nt][i] = 0.f;

    auto load_chunk = [&](int c, int buf) {
        const int ko = c * 32;
        #pragma unroll
        for (int pl = 0; pl < 3; pl++) {
            const uint32_t da = sts_a + buf * 30720 + pl * 10240;
            CP16(da,      ga[pl] + ko);
            CP16(da + 16, ga[pl] + ko + 8);
            const uint32_t db = sts_b + buf * 15360 + pl * 5120;
            CP16(db, gb[pl] + ko);
        }
    };

    const uint32_t a_lane = (uint32_t)((lane & 15) * 80 + (lane >> 4) * 16);
    const uint32_t b_lane = (uint32_t)((lane & 7) * 80 + ((lane >> 3) & 1) * 16 + (lane >> 4) * 640);
    const uint32_t abase0 = sbase + warp_o * 5120 + a_lane;
    const uint32_t bbase0 = sbB + warp_n * 1280 + b_lane;

    load_chunk(0, 0);
    CP_COMMIT();
    CP_WAIT0();
    __syncthreads();

    for (int c = 0; c < NCH; c++) {
        const int buf = c & 1;
        if (c + 1 < NCH) { load_chunk(c + 1, buf ^ 1); CP_COMMIT(); }

        float accC[4][2][4];
        #pragma unroll
        for (int mt = 0; mt < 4; mt++)
            #pragma unroll
            for (int nt = 0; nt < 2; nt++)
                #pragma unroll
                for (int i = 0; i < 4; i++) accC[mt][nt][i] = 0.f;

        #pragma unroll
        for (int ks = 0; ks < 2; ks++) {
            uint32_t bfr[3][4];
            const uint32_t bb = bbase0 + buf * 15360 + ks * 32;
            #pragma unroll
            for (int p = 0; p < 3; p++)
                ldsm4(bfr[p], bb + p * 5120);

            const uint32_t ab = abase0 + buf * 30720 + ks * 32;
            uint32_t af[4][4];
            #pragma unroll
            for (int mt = 0; mt < 4; mt++) ldsm4(af[mt], ab + mt * 1280);
            #pragma unroll
            for (int pb = 0; pb < 3; pb++)
                #pragma unroll
                for (int mt = 0; mt < 4; mt++)
                    #pragma unroll
                    for (int nt = 0; nt < 2; nt++)
                        mma_bf16(accC[mt][nt], af[mt], &bfr[pb][nt * 2]);
            #pragma unroll
            for (int mt = 0; mt < 4; mt++) ldsm4(af[mt], ab + 10240 + mt * 1280);
            #pragma unroll
            for (int pb = 0; pb < 2; pb++)
                #pragma unroll
                for (int mt = 0; mt < 4; mt++)
                    #pragma unroll
                    for (int nt = 0; nt < 2; nt++)
                        mma_bf16(accC[mt][nt], af[mt], &bfr[pb][nt * 2]);
            #pragma unroll
            for (int mt = 0; mt < 4; mt++) ldsm4(af[mt], ab + 20480 + mt * 1280);
            #pragma unroll
            for (int mt = 0; mt < 4; mt++)
                #pragma unroll
                for (int nt = 0; nt < 2; nt++)
                    mma_bf16(accC[mt][nt], af[mt], &bfr[0][nt * 2]);
        }

        #pragma unroll
        for (int mt = 0; mt < 4; mt++)
            #pragma unroll
            for (int nt = 0; nt < 2; nt++)
                #pragma unroll
                for (int i = 0; i < 4; i++)
                    accT[mt][nt][i] = __fadd_rn(accT[mt][nt][i], accC[mt][nt][i]);

        if (c + 1 < NCH) CP_WAIT0();
        __syncthreads();
    }

    // ---- epilogue ----
    float* es = reinterpret_cast<float*>(smem);   // [64][132]
    #pragma unroll
    for (int mt = 0; mt < 4; mt++)
        #pragma unroll
        for (int nt = 0; nt < 2; nt++)
            #pragma unroll
            for (int i = 0; i < 4; i++) {
                int ol = warp_o * 64 + mt * 16 + (lane >> 2) + 8 * (i >> 1);
                int nl = warp_n * 16 + nt * 8 + 2 * (lane & 3) + (i & 1);
                es[nl * 132 + ol] = accT[mt][nt][i];
            }
    __syncthreads();
    for (int it = tid; it < 64 * 32; it += 256) {
        int nl = it >> 5;
        int c4 = (it & 31) * 4;
        int o  = o0 + c4;
        if (o < O) {
            float4 v  = *reinterpret_cast<const float4*>(&es[nl * 132 + c4]);
            float4 bv = *reinterpret_cast<const float4*>(&bias[o]);
            v.x = __fadd_rn(v.x, bv.x);
            v.y = __fadd_rn(v.y, bv.y);
            v.z = __fadd_rn(v.z, bv.z);
            v.w = __fadd_rn(v.w, bv.w);
            if (!SEL) {
                v.x = fmaxf(v.x, 0.f); v.y = fmaxf(v.y, 0.f);
                v.z = fmaxf(v.z, 0.f); v.w = fmaxf(v.w, 0.f);
            }
            *reinterpret_cast<float4*>(&Y[(n0 + nl) * O + o]) = v;
        }
    }
}

// ---------------------------------------------------------------------------
// Threefry2x32-20, key=(0,42); partitionable path (verified bit-exact)
// ---------------------------------------------------------------------------
__device__ __forceinline__ unsigned rotl32(unsigned x, int r) {
    return (x << r) | (x >> (32 - r));
}
__device__ __forceinline__ void threefry2x32_k42(unsigned c0, unsigned c1,
                                                 unsigned& o0, unsigned& o1) {
    const unsigned k0 = 0u, k1 = 42u;
    const unsigned k2 = 0x1BD11BDAu ^ k0 ^ k1;
    unsigned x0 = c0 + k0;
    unsigned x1 = c1 + k1;
#define TFR(r) { x0 += x1; x1 = rotl32(x1, (r)); x1 ^= x0; }
    TFR(13) TFR(15) TFR(26) TFR(6)
    x0 += k1; x1 += k2 + 1u;
    TFR(17) TFR(29) TFR(16) TFR(24)
    x0 += k2; x1 += k0 + 2u;
    TFR(13) TFR(15) TFR(26) TFR(6)
    x0 += k0; x1 += k1 + 3u;
    TFR(17) TFR(29) TFR(16) TFR(24)
    x0 += k1; x1 += k2 + 4u;
    TFR(13) TFR(15) TFR(26) TFR(6)
    x0 += k2; x1 += k0 + 5u;
#undef TFR
    o0 = x0; o1 = x1;
}
__device__ __forceinline__ float xla_erfinv32(float x) {
    float w = -log1pf(__fmul_rn(-x, x));
    float p;
    if (w < 5.0f) {
        w = __fadd_rn(w, -2.5f);
        p = 2.81022636e-08f;
        p = __fadd_rn(__fmul_rn(p, w),  3.43273939e-07f);
        p = __fadd_rn(__fmul_rn(p, w), -3.5233877e-06f);
        p = __fadd_rn(__fmul_rn(p, w), -4.39150654e-06f);
        p = __fadd_rn(__fmul_rn(p, w),  0.00021858087f);
        p = __fadd_rn(__fmul_rn(p, w), -0.00125372503f);
        p = __fadd_rn(__fmul_rn(p, w), -0.00417768164f);
        p = __fadd_rn(__fmul_rn(p, w),  0.246640727f);
        p = __fadd_rn(__fmul_rn(p, w),  1.50140941f);
    } else {
        w = __fadd_rn(sqrtf(w), -3.0f);
        p = -0.000200214257f;
        p = __fadd_rn(__fmul_rn(p, w),  0.000100950558f);
        p = __fadd_rn(__fmul_rn(p, w),  0.00134934322f);
        p = __fadd_rn(__fmul_rn(p, w), -0.00367342844f);
        p = __fadd_rn(__fmul_rn(p, w),  0.00573950773f);
        p = __fadd_rn(__fmul_rn(p, w), -0.0076224613f);
        p = __fadd_rn(__fmul_rn(p, w),  0.00943887047f);
        p = __fadd_rn(__fmul_rn(p, w),  1.00167406f);
        p = __fadd_rn(__fmul_rn(p, w),  2.83297682f);
    }
    return __fmul_rn(p, x);
}
__device__ __forceinline__ float jax_normal_eps(unsigned i) {
    unsigned r0, r1;
    threefry2x32_k42(0u, i, r0, r1);
    unsigned bits = r0 ^ r1;
    float f = __fadd_rn(__uint_as_float((bits >> 9) | 0x3f800000u), -1.0f);
    float u = fmaxf(-0.99999994f, __fadd_rn(__fmul_rn(f, 2.0f), -0.99999994f));
    return __fmul_rn(1.41421356237309515f, xla_erfinv32(u));
}

// ---------------------------------------------------------------------------
// eps precompute (runs on side stream, concurrent with GEMM1)
// ---------------------------------------------------------------------------
__global__ __launch_bounds__(256)
void eps_kernel() {
    unsigned i = blockIdx.x * 256u + threadIdx.x;
    if (i < (unsigned)(B_ * FHID * T_))
        g_eps[i] = jax_normal_eps(i);
}

// ---------------------------------------------------------------------------
// coding = mu + eps * exp(0.5*ln_var); psp2 = dual-exp IIR; emit bf16x3 planes
// (eps read from precomputed buffer; identical values)
// ---------------------------------------------------------------------------
__global__ __launch_bounds__(256)
void coding_psp2_kernel() {
    int idx = blockIdx.x * blockDim.x + threadIdx.x;   // b*500+f
    if (idx >= B_ * FHID) return;
    int b = idx / FHID;
    int f = idx - b * FHID;
    const float* mu = g_ann + b * (T_ * 1000) + f;
    const float* lv = mu + FHID;
    if (f < 12) {
        bf16 z = __float2bfloat16(0.f);
        for (int t = 0; t < T_; t++) {
            int zi = (b * T_ + t) * 512 + FHID + f;
            g_p2p[0][zi] = z; g_p2p[1][zi] = z; g_p2p[2][zi] = z;
        }
    }
    const float* ep = g_eps + (unsigned)idx * 100u;
    float y1 = 0.f, y2 = 0.f;
    #pragma unroll 4
    for (int t = 0; t < T_; t++) {
        float eps = ep[t];
        float sc  = expf(__fmul_rn(0.5f, lv[t * 1000]));
        float cod = __fadd_rn(mu[t * 1000], __fmul_rn(eps, sc));
        float y   = __fadd_rn(__fadd_rn(__fmul_rn(A1F, y1), __fmul_rn(A2F, y2)), cod);
        bf16 b0, b1, b2;
        split3(y, b0, b1, b2);
        int oi = (b * T_ + t) * 512 + f;
        g_p2p[0][oi] = b0;
        g_p2p[1][oi] = b1;
        g_p2p[2][oi] = b2;
        y2 = y1; y1 = y;
    }
}

// ---------------------------------------------------------------------------
// LIF2 + IIR -> g_psp3 [n,500]
// ---------------------------------------------------------------------------
__global__ __launch_bounds__(256)
void lif2_psp3_kernel() {
    int idx = blockIdx.x * blockDim.x + threadIdx.x;
    if (idx >= B_ * FHID) return;
    int b = idx / FHID;
    int f = idx - b * FHID;
    const float* c = g_cur2 + b * (T_ * FHID) + f;
    float* out     = g_psp3 + b * (T_ * FHID) + f;
    float v = 0.f, s = 0.f, y1 = 0.f, y2 = 0.f;
    #pragma unroll 4
    for (int t = 0; t < T_; t++) {
        float vn = __fadd_rn(__fmul_rn(__fmul_rn(v, EMF), __fsub_rn(1.0f, s)), c[t * FHID]);
        float spk = (vn > 1.0f) ? 1.0f : 0.0f;
        v = vn; s = spk;
        float y = __fadd_rn(__fadd_rn(__fmul_rn(A1F, y1), __fmul_rn(A2F, y2)), spk);
        out[t * FHID] = y;
        y2 = y1; y1 = y;
    }
}

// ---------------------------------------------------------------------------
// GEMM3 (fp32, tiny)
// ---------------------------------------------------------------------------
__global__ __launch_bounds__(256)
void gemm3_kernel(const float* __restrict__ W3, const float* __restrict__ b3) {
    __shared__ __align__(16) float Ws[FOUT * FHID];
    for (int i = threadIdx.x; i < FOUT * FHID; i += 256) Ws[i] = W3[i];
    __syncthreads();
    int n = blockIdx.x * 256 + threadIdx.x;
    float acc[FOUT];
    #pragma unroll
    for (int o = 0; o < FOUT; o++) acc[o] = 0.f;
    const float4* xp = reinterpret_cast<const float4*>(g_psp3 + n * FHID);
    #pragma unroll 5
    for (int k4 = 0; k4 < FHID / 4; k4++) {
        float4 x = xp[k4];
        #pragma unroll
        for (int o = 0; o < FOUT; o++) {
            float4 w = *reinterpret_cast<const float4*>(&Ws[o * FHID + k4 * 4]);
            acc[o] += w.x * x.x;
            acc[o] += w.y * x.y;
            acc[o] += w.z * x.z;
            acc[o] += w.w * x.w;
        }
    }
    #pragma unroll
    for (int o = 0; o < FOUT; o++)
        g_cur3[n * FOUT + o] = __fadd_rn(acc[o], b3[o]);
}

// ---------------------------------------------------------------------------
// LIF3 -> output spikes [b,o,t]
// ---------------------------------------------------------------------------
__global__ __launch_bounds__(256)
void lif3_kernel(float* __restrict__ out) {
    int idx = blockIdx.x * blockDim.x + threadIdx.x;
    if (idx >= B_ * FOUT) return;
    int b = idx / FOUT;
    int o = idx - b * FOUT;
    const float* c = g_cur3 + b * (T_ * FOUT) + o;
    float* op = out + idx * T_;
    float v = 0.f, s = 0.f;
    #pragma unroll 4
    for (int t = 0; t < T_; t++) {
        float vn = __fadd_rn(__fmul_rn(__fmul_rn(v, EMF), __fsub_rn(1.0f, s)), c[t * FOUT]);
        float spk = (vn > 1.0f) ? 1.0f : 0.0f;
        v = vn; s = spk;
        op[t] = spk;
    }
}

// ---------------------------------------------------------------------------
extern "C" void kernel_launch(void* const* d_in, const int* in_sizes, int n_in,
                              void* d_out, int out_size) {
    const float* inputs = (const float*)d_in[0];
    const float* W1     = (const float*)d_in[1];
    const float* b1     = (const float*)d_in[2];
    const float* W2     = (const float*)d_in[3];
    const float* b2     = (const float*)d_in[4];
    const float* W3     = (const float*)d_in[5];
    const float* b3     = (const float*)d_in[6];
    float* out          = (float*)d_out;

    constexpr int GEMM_SMEM = 92160;
    cudaFuncSetAttribute(gemm_b3<0>, cudaFuncAttributeMaxDynamicSharedMemorySize, GEMM_SMEM);
    cudaFuncSetAttribute(gemm_b3<1>, cudaFuncAttributeMaxDynamicSharedMemorySize, GEMM_SMEM);

    // Side stream + fork/join events (capture-legal multi-branch graph)
    cudaStream_t s1;
    cudaStreamCreateWithFlags(&s1, cudaStreamNonBlocking);
    cudaEvent_t ev_fork, ev_join;
    cudaEventCreateWithFlags(&ev_fork, cudaEventDisableTiming);
    cudaEventCreateWithFlags(&ev_join, cudaEventDisableTiming);

    // Main stream: prep for GEMM1
    split_w_kernel<0><<<(1024 * 800 + 255) / 256, 256>>>(W1);
    transpose_split_inputs<<<dim3(25, 256), 256>>>(inputs);

    // Fork: eps precompute + W2 split run concurrent with GEMM1
    cudaEventRecord(ev_fork, 0);
    cudaStreamWaitEvent(s1, ev_fork, 0);
    eps_kernel<<<(B_ * FHID * T_ + 255) / 256, 256, 0, s1>>>();
    split_w_kernel<1><<<(512 * 512 + 255) / 256, 256, 0, s1>>>(W2);
    cudaEventRecord(ev_join, s1);

    // Main stream: GEMM1 (tensor-bound; overlaps the ALU-bound eps kernel)
    gemm_b3<0><<<dim3(8, 400), 256, GEMM_SMEM>>>(b1);

    // Join before coding (needs g_eps) and GEMM2 (needs g_w2p)
    cudaStreamWaitEvent(0, ev_join, 0);

    coding_psp2_kernel<<<(B_ * FHID + 255) / 256, 256>>>();
    gemm_b3<1><<<dim3(4, 400), 256, GEMM_SMEM>>>(b2);
    lif2_psp3_kernel<<<(B_ * FHID + 255) / 256, 256>>>();
    gemm3_kernel<<<NTOK / 256, 256>>>(W3, b3);
    lif3_kernel<<<(B_ * FOUT + 255) / 256, 256>>>(out);

    cudaEventDestroy(ev_fork);
    cudaEventDestroy(ev_join);
    cudaStreamDestroy(s1);
}